// round 1
// baseline (speedup 1.0000x reference)
#include <cuda_runtime.h>

#define SEQ 4096
#define DIM 1024
#define NH  16
#define DH  64

// Scratch (device globals; no allocation allowed)
__device__ float g_Q[SEQ * DIM];
__device__ float g_K[SEQ * DIM];
__device__ float g_V[SEQ * DIM];
__device__ float g_C[SEQ * DIM];

// ---------------------------------------------------------------------------
// Generic 64x64-tile GEMM:  C[m, n0+c] = sum_k A[m,k] * B'[k,c] + bias[n0+c]
//   A: [4096, 1024] row-major (lda = 1024)
//   B tile base = B + blockIdx.y * bTileStride; element (k,c) at k*bRowStride + c
//   C: [4096, 1024] row-major (ldc = 1024), column base n0 = blockIdx.y*64
// Covers:
//   per-head projections: W [H, D, DH] -> bTileStride = D*DH, bRowStride = DH
//   output projection:    Wo [D, D]    -> bTileStride = 64,   bRowStride = D
// ---------------------------------------------------------------------------
__global__ void gemm64_kernel(const float* __restrict__ A,
                              const float* __restrict__ B,
                              const float* __restrict__ bias,
                              float* __restrict__ C,
                              long bTileStride, int bRowStride)
{
    const int m0 = blockIdx.x * 64;
    const int n0 = blockIdx.y * 64;
    const float* Bb = B + (long)blockIdx.y * bTileStride;

    __shared__ float As[16 * 68];   // As[kk][r], stride 68 (aligned float4, low conflict)
    __shared__ float Bs[16 * 64];   // Bs[kk][c]

    const int tid = threadIdx.x;
    const int tx = tid & 15;
    const int ty = tid >> 4;
    const int r0 = ty * 4;
    const int c0 = tx * 4;

    float acc[4][4] = {};

    for (int k0 = 0; k0 < DIM; k0 += 16) {
        // Load A tile: 64 rows x 16 k  (transposed store)
        #pragma unroll
        for (int l = 0; l < 4; l++) {
            int idx = tid + 256 * l;
            int r = idx >> 4;
            int kk = idx & 15;
            As[kk * 68 + r] = A[(long)(m0 + r) * DIM + k0 + kk];
        }
        // Load B tile: 16 k x 64 cols
        #pragma unroll
        for (int l = 0; l < 4; l++) {
            int idx = tid + 256 * l;
            int kk = idx >> 6;
            int c = idx & 63;
            Bs[kk * 64 + c] = Bb[(long)(k0 + kk) * bRowStride + c];
        }
        __syncthreads();

        #pragma unroll
        for (int kk = 0; kk < 16; kk++) {
            float4 a4 = *(const float4*)&As[kk * 68 + r0];
            float4 b4 = *(const float4*)&Bs[kk * 64 + c0];
            float av[4] = {a4.x, a4.y, a4.z, a4.w};
            float bv[4] = {b4.x, b4.y, b4.z, b4.w};
            #pragma unroll
            for (int i = 0; i < 4; i++)
                #pragma unroll
                for (int j = 0; j < 4; j++)
                    acc[i][j] = fmaf(av[i], bv[j], acc[i][j]);
        }
        __syncthreads();
    }

    #pragma unroll
    for (int i = 0; i < 4; i++) {
        #pragma unroll
        for (int j = 0; j < 4; j++) {
            C[(long)(m0 + r0 + i) * DIM + n0 + c0 + j] =
                acc[i][j] + bias[n0 + c0 + j];
        }
    }
}

// ---------------------------------------------------------------------------
// Flash attention (fp32, non-causal), one (q-block, head) per CTA.
//   Q/K/V: [S, 1024] with head h at columns [h*64, h*64+64)
//   Out:   same layout (concat-of-heads done implicitly)
// BQ = BK = 64, DH = 64. Online softmax.
// ---------------------------------------------------------------------------
#define ATT_STRIDE 68
#define ATT_SMEM_BYTES (3 * 64 * ATT_STRIDE * 4 + 3 * 64 * 4)

__global__ void attn_kernel(const float* __restrict__ Q,
                            const float* __restrict__ K,
                            const float* __restrict__ V,
                            float* __restrict__ Out)
{
    extern __shared__ float sm[];
    float* Qs  = sm;                       // 64 x 68
    float* KVs = sm + 64 * ATT_STRIDE;     // 64 x 68
    float* Ss  = sm + 2 * 64 * ATT_STRIDE; // 64 x 68
    float* m_s = sm + 3 * 64 * ATT_STRIDE; // 64
    float* l_s = m_s + 64;                 // 64
    float* a_s = l_s + 64;                 // 64

    const int qb = blockIdx.x;
    const int h  = blockIdx.y;
    const int tid = threadIdx.x;
    const int tx = tid & 15;
    const int ty = tid >> 4;
    const int r0 = ty * 4;
    const int c0 = tx * 4;
    const int colbase = h * 64;

    // Load Q block, pre-scaled by 1/sqrt(D) = 1/32
    #pragma unroll
    for (int l = 0; l < 16; l++) {
        int idx = tid + 256 * l;
        int r = idx >> 6;
        int c = idx & 63;
        Qs[r * ATT_STRIDE + c] =
            Q[(long)(qb * 64 + r) * DIM + colbase + c] * 0.03125f;
    }
    if (tid < 64) { m_s[tid] = -1e30f; l_s[tid] = 0.0f; }

    float o[4][4] = {};
    __syncthreads();

    for (int kb = 0; kb < SEQ / 64; kb++) {
        // Load K block (KVs free: prev PV finished before loop-end sync)
        #pragma unroll
        for (int l = 0; l < 16; l++) {
            int idx = tid + 256 * l;
            int r = idx >> 6;
            int c = idx & 63;
            KVs[r * ATT_STRIDE + c] =
                K[(long)(kb * 64 + r) * DIM + colbase + c];
        }
        __syncthreads();

        // S = Q * K^T  (64x64), 4x4 per thread, vectorized along k
        float s[4][4] = {};
        #pragma unroll
        for (int k = 0; k < 64; k += 4) {
            float4 qa[4], ka[4];
            #pragma unroll
            for (int i = 0; i < 4; i++)
                qa[i] = *(const float4*)&Qs[(r0 + i) * ATT_STRIDE + k];
            #pragma unroll
            for (int j = 0; j < 4; j++)
                ka[j] = *(const float4*)&KVs[(c0 + j) * ATT_STRIDE + k];
            #pragma unroll
            for (int i = 0; i < 4; i++) {
                #pragma unroll
                for (int j = 0; j < 4; j++) {
                    s[i][j] = fmaf(qa[i].x, ka[j].x, s[i][j]);
                    s[i][j] = fmaf(qa[i].y, ka[j].y, s[i][j]);
                    s[i][j] = fmaf(qa[i].z, ka[j].z, s[i][j]);
                    s[i][j] = fmaf(qa[i].w, ka[j].w, s[i][j]);
                }
            }
        }
        #pragma unroll
        for (int i = 0; i < 4; i++)
            #pragma unroll
            for (int j = 0; j < 4; j++)
                Ss[(r0 + i) * ATT_STRIDE + c0 + j] = s[i][j];
        __syncthreads();   // Ss complete; K reads complete

        // Online softmax (one thread per row) — exp written back into Ss
        if (tid < 64) {
            float mo = m_s[tid];
            float mx = mo;
            #pragma unroll 8
            for (int c = 0; c < 64; c++)
                mx = fmaxf(mx, Ss[tid * ATT_STRIDE + c]);
            float al = __expf(mo - mx);
            float sum = 0.0f;
            #pragma unroll 8
            for (int c = 0; c < 64; c++) {
                float p = __expf(Ss[tid * ATT_STRIDE + c] - mx);
                Ss[tid * ATT_STRIDE + c] = p;
                sum += p;
            }
            l_s[tid] = l_s[tid] * al + sum;
            m_s[tid] = mx;
            a_s[tid] = al;
        }

        // Load V block into KVs (safe: all K reads finished at the sync above)
        #pragma unroll
        for (int l = 0; l < 16; l++) {
            int idx = tid + 256 * l;
            int r = idx >> 6;
            int c = idx & 63;
            KVs[r * ATT_STRIDE + c] =
                V[(long)(kb * 64 + r) * DIM + colbase + c];
        }
        __syncthreads();   // V + softmax + alpha ready

        // O = O * alpha + P * V
        float al_r[4];
        #pragma unroll
        for (int i = 0; i < 4; i++) al_r[i] = a_s[r0 + i];
        #pragma unroll
        for (int i = 0; i < 4; i++)
            #pragma unroll
            for (int j = 0; j < 4; j++)
                o[i][j] *= al_r[i];

        #pragma unroll
        for (int k = 0; k < 64; k += 4) {
            float4 pr[4], vr[4];
            #pragma unroll
            for (int i = 0; i < 4; i++)
                pr[i] = *(const float4*)&Ss[(r0 + i) * ATT_STRIDE + k];
            #pragma unroll
            for (int kk = 0; kk < 4; kk++)
                vr[kk] = *(const float4*)&KVs[(k + kk) * ATT_STRIDE + c0];
            #pragma unroll
            for (int i = 0; i < 4; i++) {
                float pv[4] = {pr[i].x, pr[i].y, pr[i].z, pr[i].w};
                #pragma unroll
                for (int kk = 0; kk < 4; kk++) {
                    o[i][0] = fmaf(pv[kk], vr[kk].x, o[i][0]);
                    o[i][1] = fmaf(pv[kk], vr[kk].y, o[i][1]);
                    o[i][2] = fmaf(pv[kk], vr[kk].z, o[i][2]);
                    o[i][3] = fmaf(pv[kk], vr[kk].w, o[i][3]);
                }
            }
        }
        __syncthreads();   // protect KVs/Ss before next iteration overwrites
    }

    // Epilogue: normalize by l and write
    float inv_l[4];
    #pragma unroll
    for (int i = 0; i < 4; i++) inv_l[i] = 1.0f / l_s[r0 + i];
    #pragma unroll
    for (int i = 0; i < 4; i++)
        #pragma unroll
        for (int j = 0; j < 4; j++)
            Out[(long)(qb * 64 + r0 + i) * DIM + colbase + c0 + j] =
                o[i][j] * inv_l[i];
}

// ---------------------------------------------------------------------------
// kernel_launch
// Inputs: q, k, v, Wq, bq, Wk, bk, Wv, bv, Wo, bo
// ---------------------------------------------------------------------------
extern "C" void kernel_launch(void* const* d_in, const int* in_sizes, int n_in,
                              void* d_out, int out_size)
{
    const float* q  = (const float*)d_in[0];
    const float* k  = (const float*)d_in[1];
    const float* v  = (const float*)d_in[2];
    const float* Wq = (const float*)d_in[3];
    const float* bq = (const float*)d_in[4];
    const float* Wk = (const float*)d_in[5];
    const float* bk = (const float*)d_in[6];
    const float* Wv = (const float*)d_in[7];
    const float* bv = (const float*)d_in[8];
    const float* Wo = (const float*)d_in[9];
    const float* bo = (const float*)d_in[10];
    float* out = (float*)d_out;

    float *Qp, *Kp, *Vp, *Cp;
    cudaGetSymbolAddress((void**)&Qp, g_Q);
    cudaGetSymbolAddress((void**)&Kp, g_K);
    cudaGetSymbolAddress((void**)&Vp, g_V);
    cudaGetSymbolAddress((void**)&Cp, g_C);

    cudaFuncSetAttribute(attn_kernel,
                         cudaFuncAttributeMaxDynamicSharedMemorySize,
                         ATT_SMEM_BYTES);

    dim3 grid(SEQ / 64, NH);
    dim3 blk(256);

    // Per-head projections: W[H, D, DH] -> tile stride D*DH, row stride DH
    gemm64_kernel<<<grid, blk>>>(q, Wq, bq, Qp, (long)DIM * DH, DH);
    gemm64_kernel<<<grid, blk>>>(k, Wk, bk, Kp, (long)DIM * DH, DH);
    gemm64_kernel<<<grid, blk>>>(v, Wv, bv, Vp, (long)DIM * DH, DH);

    // Attention
    attn_kernel<<<grid, blk, ATT_SMEM_BYTES>>>(Qp, Kp, Vp, Cp);

    // Output projection: Wo[D, D] -> tile stride 64 (column offset), row stride D
    gemm64_kernel<<<grid, blk>>>(Cp, Wo, bo, out, 64L, DIM);
}

// round 3
// speedup vs baseline: 3.1652x; 3.1652x over previous
#include <cuda_runtime.h>

#define SEQ 4096
#define DIM 1024
#define NH  16
#define DH  64

// Scratch (device globals; no allocation allowed)
__device__ float g_Q[SEQ * DIM];
__device__ float g_K[SEQ * DIM];
__device__ float g_V[SEQ * DIM];
__device__ float g_C[SEQ * DIM];

// ---------------------------------------------------------------------------
// helpers
// ---------------------------------------------------------------------------
__device__ __forceinline__ unsigned f2t(float f) {
    unsigned u; asm("cvt.rna.tf32.f32 %0, %1;" : "=r"(u) : "f"(f)); return u;
}
__device__ __forceinline__ float f2tf(float f) { return __uint_as_float(f2t(f)); }
__device__ __forceinline__ float ex2f(float x) {
    float r; asm("ex2.approx.ftz.f32 %0, %1;" : "=f"(r) : "f"(x)); return r;
}
__device__ __forceinline__ void mma8(float* c,
                                     unsigned a0, unsigned a1, unsigned a2, unsigned a3,
                                     unsigned b0, unsigned b1) {
    asm volatile(
        "mma.sync.aligned.m16n8k8.row.col.f32.tf32.tf32.f32 "
        "{%0,%1,%2,%3},{%4,%5,%6,%7},{%8,%9},{%0,%1,%2,%3};"
        : "+f"(c[0]), "+f"(c[1]), "+f"(c[2]), "+f"(c[3])
        : "r"(a0), "r"(a1), "r"(a2), "r"(a3), "r"(b0), "r"(b1));
}

// ---------------------------------------------------------------------------
// tf32 tensor-core GEMM: C[4096,1024] tile = A[4096,1024] x B-tile[1024,64]
// CTA tile 256(M) x 64(N), K-step 32. 8 warps: warp tile 64(M) x 32(N).
//   per-head projections: W[H,D,DH] -> bTileStride = D*DH, bRowStride = DH
//   output projection:    Wo[D,D]   -> bTileStride = 64,   bRowStride = D
// ---------------------------------------------------------------------------
__global__ __launch_bounds__(256) void gemm_tc(const float* __restrict__ A,
                                               const float* __restrict__ B,
                                               const float* __restrict__ bias,
                                               float* __restrict__ C,
                                               long bTileStride, int bRowStride)
{
    __shared__ float As[256][36];   // [row][k], stride 36 -> 4g+tg bank pattern
    __shared__ float Bs[32][72];    // [k][col],  stride 72 -> 8tg+g bank pattern

    const int tid  = threadIdx.x;
    const int lane = tid & 31;
    const int warp = tid >> 5;
    const int g    = lane >> 2;
    const int tg   = lane & 3;
    const int mw   = (warp >> 1) * 64;   // warp row base (0,64,128,192)
    const int nw   = (warp & 1) * 32;    // warp col base (0,32)
    const int m0   = blockIdx.x * 256;
    const int n0   = blockIdx.y * 64;
    const float* Bb = B + (long)blockIdx.y * bTileStride;

    const int brow = tid >> 3;           // 0..31
    const int bcol = (tid & 7) * 8;      // 0..56

    float acc[4][4][4] = {};

    for (int k0 = 0; k0 < DIM; k0 += 32) {
        // A tile: row = tid, 32 k values
        const float* Ar = A + (long)(m0 + tid) * DIM + k0;
        #pragma unroll
        for (int c = 0; c < 32; c += 4) {
            float4 v = *(const float4*)(Ar + c);
            float4 w;
            w.x = f2tf(v.x); w.y = f2tf(v.y); w.z = f2tf(v.z); w.w = f2tf(v.w);
            *(float4*)&As[tid][c] = w;
        }
        // B tile: 32 k x 64 cols
        const float* Br = Bb + (long)(k0 + brow) * bRowStride + bcol;
        #pragma unroll
        for (int c = 0; c < 8; c += 4) {
            float4 v = *(const float4*)(Br + c);
            float4 w;
            w.x = f2tf(v.x); w.y = f2tf(v.y); w.z = f2tf(v.z); w.w = f2tf(v.w);
            *(float4*)&Bs[brow][bcol + c] = w;
        }
        __syncthreads();

        #pragma unroll
        for (int kb = 0; kb < 4; kb++) {
            unsigned a[4][4], b[4][2];
            #pragma unroll
            for (int i = 0; i < 4; i++) {
                int r = mw + 16 * i + g;
                int c = kb * 8 + tg;
                a[i][0] = __float_as_uint(As[r][c]);
                a[i][1] = __float_as_uint(As[r + 8][c]);
                a[i][2] = __float_as_uint(As[r][c + 4]);
                a[i][3] = __float_as_uint(As[r + 8][c + 4]);
            }
            #pragma unroll
            for (int j = 0; j < 4; j++) {
                b[j][0] = __float_as_uint(Bs[kb * 8 + tg][nw + 8 * j + g]);
                b[j][1] = __float_as_uint(Bs[kb * 8 + tg + 4][nw + 8 * j + g]);
            }
            #pragma unroll
            for (int i = 0; i < 4; i++)
                #pragma unroll
                for (int j = 0; j < 4; j++)
                    mma8(acc[i][j], a[i][0], a[i][1], a[i][2], a[i][3],
                         b[j][0], b[j][1]);
        }
        __syncthreads();
    }

    // epilogue + bias
    #pragma unroll
    for (int i = 0; i < 4; i++) {
        int row = m0 + mw + 16 * i + g;
        #pragma unroll
        for (int j = 0; j < 4; j++) {
            int col = n0 + nw + 8 * j + 2 * tg;
            float b0v = bias[col], b1v = bias[col + 1];
            float2 lo = make_float2(acc[i][j][0] + b0v, acc[i][j][1] + b1v);
            float2 hi = make_float2(acc[i][j][2] + b0v, acc[i][j][3] + b1v);
            *(float2*)&C[(long)row * DIM + col]       = lo;
            *(float2*)&C[(long)(row + 8) * DIM + col] = hi;
        }
    }
}

// ---------------------------------------------------------------------------
// Flash attention, tf32 tensor cores. CTA: 128 Q-rows x 1 head, 8 warps
// (warp = 16 Q-rows). KV block = 64 rows. Q fragments live in registers.
// Softmax fully in registers (quad shuffles + ex2.approx).
// P routed via smem (C-frag -> A-frag layout change for tf32).
// ---------------------------------------------------------------------------
#define APS 68   // Ps stride (4g+tg pattern for A-frags)
#define AKS 68   // Ks stride (B-frag 4g+tg pattern)
#define AVS 72   // Vs stride (B-frag 8tg+g pattern)
#define ATT_SMEM_BYTES ((128 * APS + 64 * AKS + 64 * AVS) * 4)

__global__ __launch_bounds__(256) void attn_tc(const float* __restrict__ Q,
                                               const float* __restrict__ K,
                                               const float* __restrict__ V,
                                               float* __restrict__ Out)
{
    extern __shared__ float sm[];
    float (*Ps)[APS] = (float(*)[APS])sm;                       // 128 x 68 (Qs at start)
    float (*Ks)[AKS] = (float(*)[AKS])(sm + 128 * APS);         // 64 x 68
    float (*Vs)[AVS] = (float(*)[AVS])(sm + 128 * APS + 64 * AKS); // 64 x 72

    const int tid  = threadIdx.x;
    const int lane = tid & 31;
    const int warp = tid >> 5;
    const int g    = lane >> 2;
    const int tg   = lane & 3;
    const int qb   = blockIdx.x;
    const int h    = blockIdx.y;
    const int colbase = h * 64;
    const int rw   = warp * 16;          // warp's q-row base in tile

    const float L2E = 1.44269504f;

    // ---- load Q tile (pre-scaled by 1/32, tf32) into Ps-as-Qs ----
    {
        int row = tid >> 1;
        int cb  = (tid & 1) * 32;
        const float* Qr = Q + (long)(qb * 128 + row) * DIM + colbase + cb;
        #pragma unroll
        for (int c = 0; c < 32; c += 4) {
            float4 v = *(const float4*)(Qr + c);
            float4 w;
            w.x = f2tf(v.x * 0.03125f); w.y = f2tf(v.y * 0.03125f);
            w.z = f2tf(v.z * 0.03125f); w.w = f2tf(v.w * 0.03125f);
            *(float4*)&Ps[row][cb + c] = w;
        }
    }
    __syncthreads();

    // ---- Q fragments in registers: q[kfrag e][4] ----
    unsigned q[8][4];
    #pragma unroll
    for (int e = 0; e < 8; e++) {
        int c = e * 8 + tg;
        q[e][0] = __float_as_uint(Ps[rw + g][c]);
        q[e][1] = __float_as_uint(Ps[rw + g + 8][c]);
        q[e][2] = __float_as_uint(Ps[rw + g][c + 4]);
        q[e][3] = __float_as_uint(Ps[rw + g + 8][c + 4]);
    }

    // online-softmax state (base-2 domain), rows g and g+8 of warp tile
    float m0 = -1e30f, m1 = -1e30f, l0 = 0.0f, l1 = 0.0f;
    float o[8][4] = {};

    // ---- prefetch KV block 0 ----
    const int krow = tid >> 2;           // 0..63
    const int kcol = (tid & 3) * 16;     // 0,16,32,48
    float4 kf[4], vf[4];
    {
        const float* Kr = K + (long)krow * DIM + colbase + kcol;
        const float* Vr = V + (long)krow * DIM + colbase + kcol;
        #pragma unroll
        for (int i = 0; i < 4; i++) { kf[i] = *(const float4*)(Kr + 4 * i);
                                      vf[i] = *(const float4*)(Vr + 4 * i); }
    }

    for (int kb = 0; kb < SEQ / 64; kb++) {
        __syncthreads();   // prev PV done; Ks/Vs (and Qs frag reads, iter 0) safe

        // store prefetched K/V (tf32)
        #pragma unroll
        for (int i = 0; i < 4; i++) {
            float4 w;
            w.x = f2tf(kf[i].x); w.y = f2tf(kf[i].y);
            w.z = f2tf(kf[i].z); w.w = f2tf(kf[i].w);
            *(float4*)&Ks[krow][kcol + 4 * i] = w;
            w.x = f2tf(vf[i].x); w.y = f2tf(vf[i].y);
            w.z = f2tf(vf[i].z); w.w = f2tf(vf[i].w);
            *(float4*)&Vs[krow][kcol + 4 * i] = w;
        }
        __syncthreads();

        // prefetch next block (overlaps with mma below)
        if (kb + 1 < SEQ / 64) {
            const float* Kr = K + (long)((kb + 1) * 64 + krow) * DIM + colbase + kcol;
            const float* Vr = V + (long)((kb + 1) * 64 + krow) * DIM + colbase + kcol;
            #pragma unroll
            for (int i = 0; i < 4; i++) { kf[i] = *(const float4*)(Kr + 4 * i);
                                          vf[i] = *(const float4*)(Vr + 4 * i); }
        }

        // ---- S = Q * K^T : s[nfrag j][4] ----
        float s[8][4] = {};
        #pragma unroll
        for (int e = 0; e < 8; e++) {
            #pragma unroll
            for (int j = 0; j < 8; j++) {
                unsigned b0 = __float_as_uint(Ks[j * 8 + g][e * 8 + tg]);
                unsigned b1 = __float_as_uint(Ks[j * 8 + g][e * 8 + tg + 4]);
                mma8(s[j], q[e][0], q[e][1], q[e][2], q[e][3], b0, b1);
            }
        }

        // ---- softmax (registers, base-2) ----
        float mx0 = -1e30f, mx1 = -1e30f;
        #pragma unroll
        for (int j = 0; j < 8; j++) {
            s[j][0] *= L2E; s[j][1] *= L2E; s[j][2] *= L2E; s[j][3] *= L2E;
            mx0 = fmaxf(mx0, fmaxf(s[j][0], s[j][1]));
            mx1 = fmaxf(mx1, fmaxf(s[j][2], s[j][3]));
        }
        mx0 = fmaxf(mx0, __shfl_xor_sync(0xffffffffu, mx0, 1));
        mx0 = fmaxf(mx0, __shfl_xor_sync(0xffffffffu, mx0, 2));
        mx1 = fmaxf(mx1, __shfl_xor_sync(0xffffffffu, mx1, 1));
        mx1 = fmaxf(mx1, __shfl_xor_sync(0xffffffffu, mx1, 2));

        float mn0 = fmaxf(m0, mx0), mn1 = fmaxf(m1, mx1);
        float al0 = ex2f(m0 - mn0), al1 = ex2f(m1 - mn1);
        float sum0 = 0.0f, sum1 = 0.0f;
        #pragma unroll
        for (int j = 0; j < 8; j++) {
            s[j][0] = ex2f(s[j][0] - mn0); s[j][1] = ex2f(s[j][1] - mn0);
            s[j][2] = ex2f(s[j][2] - mn1); s[j][3] = ex2f(s[j][3] - mn1);
            sum0 += s[j][0] + s[j][1];
            sum1 += s[j][2] + s[j][3];
        }
        sum0 += __shfl_xor_sync(0xffffffffu, sum0, 1);
        sum0 += __shfl_xor_sync(0xffffffffu, sum0, 2);
        sum1 += __shfl_xor_sync(0xffffffffu, sum1, 1);
        sum1 += __shfl_xor_sync(0xffffffffu, sum1, 2);
        l0 = l0 * al0 + sum0; m0 = mn0;
        l1 = l1 * al1 + sum1; m1 = mn1;

        // rescale O
        #pragma unroll
        for (int j = 0; j < 8; j++) {
            o[j][0] *= al0; o[j][1] *= al0;
            o[j][2] *= al1; o[j][3] *= al1;
        }

        // store P (tf32) to smem
        #pragma unroll
        for (int j = 0; j < 8; j++) {
            int c = j * 8 + 2 * tg;
            *(float2*)&Ps[rw + g][c]     = make_float2(f2tf(s[j][0]), f2tf(s[j][1]));
            *(float2*)&Ps[rw + g + 8][c] = make_float2(f2tf(s[j][2]), f2tf(s[j][3]));
        }
        __syncthreads();   // Ps + Vs ready

        // ---- O += P * V ----
        #pragma unroll
        for (int kbf = 0; kbf < 8; kbf++) {
            int c = kbf * 8 + tg;
            unsigned pa0 = __float_as_uint(Ps[rw + g][c]);
            unsigned pa1 = __float_as_uint(Ps[rw + g + 8][c]);
            unsigned pa2 = __float_as_uint(Ps[rw + g][c + 4]);
            unsigned pa3 = __float_as_uint(Ps[rw + g + 8][c + 4]);
            #pragma unroll
            for (int j = 0; j < 8; j++) {
                unsigned b0 = __float_as_uint(Vs[kbf * 8 + tg][j * 8 + g]);
                unsigned b1 = __float_as_uint(Vs[kbf * 8 + tg + 4][j * 8 + g]);
                mma8(o[j], pa0, pa1, pa2, pa3, b0, b1);
            }
        }
    }

    // ---- epilogue: normalize and write ----
    float il0 = 1.0f / l0, il1 = 1.0f / l1;
    int row0 = qb * 128 + rw + g;
    #pragma unroll
    for (int j = 0; j < 8; j++) {
        int col = colbase + j * 8 + 2 * tg;
        *(float2*)&Out[(long)row0 * DIM + col] =
            make_float2(o[j][0] * il0, o[j][1] * il0);
        *(float2*)&Out[(long)(row0 + 8) * DIM + col] =
            make_float2(o[j][2] * il1, o[j][3] * il1);
    }
}

// ---------------------------------------------------------------------------
// kernel_launch
// ---------------------------------------------------------------------------
extern "C" void kernel_launch(void* const* d_in, const int* in_sizes, int n_in,
                              void* d_out, int out_size)
{
    const float* q  = (const float*)d_in[0];
    const float* k  = (const float*)d_in[1];
    const float* v  = (const float*)d_in[2];
    const float* Wq = (const float*)d_in[3];
    const float* bq = (const float*)d_in[4];
    const float* Wk = (const float*)d_in[5];
    const float* bk = (const float*)d_in[6];
    const float* Wv = (const float*)d_in[7];
    const float* bv = (const float*)d_in[8];
    const float* Wo = (const float*)d_in[9];
    const float* bo = (const float*)d_in[10];
    float* out = (float*)d_out;

    float *Qp, *Kp, *Vp, *Cp;
    cudaGetSymbolAddress((void**)&Qp, g_Q);
    cudaGetSymbolAddress((void**)&Kp, g_K);
    cudaGetSymbolAddress((void**)&Vp, g_V);
    cudaGetSymbolAddress((void**)&Cp, g_C);

    cudaFuncSetAttribute(attn_tc,
                         cudaFuncAttributeMaxDynamicSharedMemorySize,
                         ATT_SMEM_BYTES);

    dim3 gg(SEQ / 256, 16);
    dim3 ag(SEQ / 128, NH);
    dim3 blk(256);

    gemm_tc<<<gg, blk>>>(q, Wq, bq, Qp, (long)DIM * DH, DH);
    gemm_tc<<<gg, blk>>>(k, Wk, bk, Kp, (long)DIM * DH, DH);
    gemm_tc<<<gg, blk>>>(v, Wv, bv, Vp, (long)DIM * DH, DH);

    attn_tc<<<ag, blk, ATT_SMEM_BYTES>>>(Qp, Kp, Vp, Cp);

    gemm_tc<<<gg, blk>>>(Cp, Wo, bo, out, 64L, DIM);
}

// round 8
// speedup vs baseline: 3.5498x; 1.1215x over previous
#include <cuda_runtime.h>

#define SEQ 4096
#define DIM 1024
#define NH  16
#define DH  64

// Scratch (device globals; no allocation allowed)
__device__ float g_Q[SEQ * DIM];
__device__ float g_K[SEQ * DIM];
__device__ float g_V[SEQ * DIM];
__device__ float g_C[SEQ * DIM];

// ---------------------------------------------------------------------------
// helpers
// ---------------------------------------------------------------------------
__device__ __forceinline__ unsigned f2t(float f) {
    unsigned u; asm("cvt.rna.tf32.f32 %0, %1;" : "=r"(u) : "f"(f)); return u;
}
__device__ __forceinline__ float f2tf(float f) { return __uint_as_float(f2t(f)); }
__device__ __forceinline__ float ex2f(float x) {
    float r; asm("ex2.approx.ftz.f32 %0, %1;" : "=f"(r) : "f"(x)); return r;
}
__device__ __forceinline__ void mma8(float* c,
                                     unsigned a0, unsigned a1, unsigned a2, unsigned a3,
                                     unsigned b0, unsigned b1) {
    asm volatile(
        "mma.sync.aligned.m16n8k8.row.col.f32.tf32.tf32.f32 "
        "{%0,%1,%2,%3},{%4,%5,%6,%7},{%8,%9},{%0,%1,%2,%3};"
        : "+f"(c[0]), "+f"(c[1]), "+f"(c[2]), "+f"(c[3])
        : "r"(a0), "r"(a1), "r"(a2), "r"(a3), "r"(b0), "r"(b1));
}
__device__ __forceinline__ void cpa16(void* dst, const void* src) {
    unsigned d = (unsigned)__cvta_generic_to_shared(dst);
    asm volatile("cp.async.cg.shared.global [%0], [%1], 16;\n"
                 :: "r"(d), "l"(src) : "memory");
}
__device__ __forceinline__ void cp_commit() {
    asm volatile("cp.async.commit_group;\n" ::: "memory");
}
template <int N> __device__ __forceinline__ void cp_wait() {
    asm volatile("cp.async.wait_group %0;\n" :: "n"(N) : "memory");
}

// ---------------------------------------------------------------------------
// tf32 tensor-core GEMM: C[4096,1024] tile = A[4096,1024] x B-tile[1024,64]
// CTA tile 256(M) x 64(N), K-step 32. 8 warps: warp tile 64(M) x 32(N).
//   per-head projections: W[H,D,DH] -> bTileStride = D*DH, bRowStride = DH
//   output projection:    Wo[D,D]   -> bTileStride = 64,   bRowStride = D
// roundOut != 0 -> round outputs to tf32 (consumed by attention as tf32)
// ---------------------------------------------------------------------------
__global__ __launch_bounds__(256) void gemm_tc(const float* __restrict__ A,
                                               const float* __restrict__ B,
                                               const float* __restrict__ bias,
                                               float* __restrict__ C,
                                               long bTileStride, int bRowStride,
                                               int roundOut)
{
    __shared__ float As[256][36];   // [row][k], stride 36 -> 4g+tg bank pattern
    __shared__ float Bs[32][72];    // [k][col],  stride 72 -> 8tg+g bank pattern

    const int tid  = threadIdx.x;
    const int lane = tid & 31;
    const int warp = tid >> 5;
    const int g    = lane >> 2;
    const int tg   = lane & 3;
    const int mw   = (warp >> 1) * 64;   // warp row base (0,64,128,192)
    const int nw   = (warp & 1) * 32;    // warp col base (0,32)
    const int m0   = blockIdx.x * 256;
    const int n0   = blockIdx.y * 64;
    const float* Bb = B + (long)blockIdx.y * bTileStride;

    const int brow = tid >> 3;           // 0..31
    const int bcol = (tid & 7) * 8;      // 0..56

    float acc[4][4][4] = {};

    for (int k0 = 0; k0 < DIM; k0 += 32) {
        // A tile: row = tid, 32 k values
        const float* Ar = A + (long)(m0 + tid) * DIM + k0;
        #pragma unroll
        for (int c = 0; c < 32; c += 4) {
            float4 v = *(const float4*)(Ar + c);
            float4 w;
            w.x = f2tf(v.x); w.y = f2tf(v.y); w.z = f2tf(v.z); w.w = f2tf(v.w);
            *(float4*)&As[tid][c] = w;
        }
        // B tile: 32 k x 64 cols
        const float* Br = Bb + (long)(k0 + brow) * bRowStride + bcol;
        #pragma unroll
        for (int c = 0; c < 8; c += 4) {
            float4 v = *(const float4*)(Br + c);
            float4 w;
            w.x = f2tf(v.x); w.y = f2tf(v.y); w.z = f2tf(v.z); w.w = f2tf(v.w);
            *(float4*)&Bs[brow][bcol + c] = w;
        }
        __syncthreads();

        #pragma unroll
        for (int kb = 0; kb < 4; kb++) {
            unsigned a[4][4], b[4][2];
            #pragma unroll
            for (int i = 0; i < 4; i++) {
                int r = mw + 16 * i + g;
                int c = kb * 8 + tg;
                a[i][0] = __float_as_uint(As[r][c]);
                a[i][1] = __float_as_uint(As[r + 8][c]);
                a[i][2] = __float_as_uint(As[r][c + 4]);
                a[i][3] = __float_as_uint(As[r + 8][c + 4]);
            }
            #pragma unroll
            for (int j = 0; j < 4; j++) {
                b[j][0] = __float_as_uint(Bs[kb * 8 + tg][nw + 8 * j + g]);
                b[j][1] = __float_as_uint(Bs[kb * 8 + tg + 4][nw + 8 * j + g]);
            }
            #pragma unroll
            for (int i = 0; i < 4; i++)
                #pragma unroll
                for (int j = 0; j < 4; j++)
                    mma8(acc[i][j], a[i][0], a[i][1], a[i][2], a[i][3],
                         b[j][0], b[j][1]);
        }
        __syncthreads();
    }

    // epilogue + bias (+ optional tf32 rounding of outputs)
    #pragma unroll
    for (int i = 0; i < 4; i++) {
        int row = m0 + mw + 16 * i + g;
        #pragma unroll
        for (int j = 0; j < 4; j++) {
            int col = n0 + nw + 8 * j + 2 * tg;
            float b0v = bias[col], b1v = bias[col + 1];
            float v0 = acc[i][j][0] + b0v, v1 = acc[i][j][1] + b1v;
            float v2 = acc[i][j][2] + b0v, v3 = acc[i][j][3] + b1v;
            if (roundOut) {
                v0 = f2tf(v0); v1 = f2tf(v1); v2 = f2tf(v2); v3 = f2tf(v3);
            }
            *(float2*)&C[(long)row * DIM + col]       = make_float2(v0, v1);
            *(float2*)&C[(long)(row + 8) * DIM + col] = make_float2(v2, v3);
        }
    }
}

// ---------------------------------------------------------------------------
// Flash attention, tf32 tensor cores. CTA: 128 Q-rows x 1 head, 8 warps
// (warp = 16 Q-rows). KV block = 64 rows, cp.async double-buffered.
// Q/K/V arrive already tf32-rounded (projection GEMM epilogue).
// Softmax fully in registers (quad shuffles + ex2.approx).
// P routed via smem (warp-private rows -> __syncwarp only).
// ---------------------------------------------------------------------------
#define APS 68   // Ps stride (4g+tg pattern for A-frags)
#define AKS 68   // Ks stride (B-frag 4g+tg pattern)
#define AVS 72   // Vs stride (B-frag 8tg+g pattern)
#define ATT_SMEM_BYTES ((128 * APS + 2 * 64 * AKS + 2 * 64 * AVS) * 4)

__global__ __launch_bounds__(256) void attn_tc(const float* __restrict__ Q,
                                               const float* __restrict__ K,
                                               const float* __restrict__ V,
                                               float* __restrict__ Out)
{
    extern __shared__ float sm[];
    float (*Ps)[APS] = (float(*)[APS])sm;                         // 128 x 68
    float (*Ks)[AKS] = (float(*)[AKS])(sm + 128 * APS);           // 2 x 64 x 68
    float (*Vs)[AVS] = (float(*)[AVS])(sm + 128 * APS + 2 * 64 * AKS); // 2 x 64 x 72

    const int tid  = threadIdx.x;
    const int lane = tid & 31;
    const int warp = tid >> 5;
    const int g    = lane >> 2;
    const int tg   = lane & 3;
    const int qb   = blockIdx.x;
    const int h    = blockIdx.y;
    const int colbase = h * 64;
    const int rw   = warp * 16;          // warp's q-row base in tile

    const float L2E = 1.44269504f;

    const int krow = tid >> 2;           // 0..63
    const int kcol = (tid & 3) * 16;     // 0,16,32,48
    const float* Kbase = K + (long)krow * DIM + colbase + kcol;
    const float* Vbase = V + (long)krow * DIM + colbase + kcol;

    // ---- issue cp.async for KV block kb into buffer kb&1 ----
    auto issue = [&](int kb) {
        int kbase = (kb & 1) * 64;
        const float* Kr = Kbase + (long)kb * 64 * DIM;
        const float* Vr = Vbase + (long)kb * 64 * DIM;
        #pragma unroll
        for (int i = 0; i < 4; i++) {
            cpa16(&Ks[kbase + krow][kcol + 4 * i], Kr + 4 * i);
            cpa16(&Vs[kbase + krow][kcol + 4 * i], Vr + 4 * i);
        }
    };

    issue(0); cp_commit();

    // ---- stage Q tile (already tf32; scale by 1/32 — exact) ----
    {
        int row = tid >> 1;
        int cb  = (tid & 1) * 32;
        const float* Qr = Q + (long)(qb * 128 + row) * DIM + colbase + cb;
        #pragma unroll
        for (int c = 0; c < 32; c += 4) {
            float4 v = *(const float4*)(Qr + c);
            v.x *= 0.03125f; v.y *= 0.03125f; v.z *= 0.03125f; v.w *= 0.03125f;
            *(float4*)&Ps[row][cb + c] = v;
        }
    }
    __syncthreads();

    // ---- Q fragments in registers: q[kfrag e][4] ----
    unsigned q[8][4];
    #pragma unroll
    for (int e = 0; e < 8; e++) {
        int c = e * 8 + tg;
        q[e][0] = __float_as_uint(Ps[rw + g][c]);
        q[e][1] = __float_as_uint(Ps[rw + g + 8][c]);
        q[e][2] = __float_as_uint(Ps[rw + g][c + 4]);
        q[e][3] = __float_as_uint(Ps[rw + g + 8][c + 4]);
    }

    // online-softmax state (base-2 domain), rows g and g+8 of warp tile
    float m0 = -1e30f, m1 = -1e30f, l0 = 0.0f, l1 = 0.0f;
    float o[8][4] = {};

    for (int kb = 0; kb < SEQ / 64; kb++) {
        cp_wait<0>();      // KV block kb resident (this thread's groups)
        __syncthreads();   // CTA-wide: data visible; prev compute done

        if (kb + 1 < SEQ / 64) issue(kb + 1);   // overlaps compute below
        cp_commit();

        const int kbase = (kb & 1) * 64;

        // ---- S = Q * K^T : s[nfrag j][4] ----
        float s[8][4] = {};
        #pragma unroll
        for (int e = 0; e < 8; e++) {
            #pragma unroll
            for (int j = 0; j < 8; j++) {
                unsigned b0 = __float_as_uint(Ks[kbase + j * 8 + g][e * 8 + tg]);
                unsigned b1 = __float_as_uint(Ks[kbase + j * 8 + g][e * 8 + tg + 4]);
                mma8(s[j], q[e][0], q[e][1], q[e][2], q[e][3], b0, b1);
            }
        }

        // ---- softmax (registers, base-2) ----
        float mx0 = -1e30f, mx1 = -1e30f;
        #pragma unroll
        for (int j = 0; j < 8; j++) {
            s[j][0] *= L2E; s[j][1] *= L2E; s[j][2] *= L2E; s[j][3] *= L2E;
            mx0 = fmaxf(mx0, fmaxf(s[j][0], s[j][1]));
            mx1 = fmaxf(mx1, fmaxf(s[j][2], s[j][3]));
        }
        mx0 = fmaxf(mx0, __shfl_xor_sync(0xffffffffu, mx0, 1));
        mx0 = fmaxf(mx0, __shfl_xor_sync(0xffffffffu, mx0, 2));
        mx1 = fmaxf(mx1, __shfl_xor_sync(0xffffffffu, mx1, 1));
        mx1 = fmaxf(mx1, __shfl_xor_sync(0xffffffffu, mx1, 2));

        float mn0 = fmaxf(m0, mx0), mn1 = fmaxf(m1, mx1);
        float al0 = ex2f(m0 - mn0), al1 = ex2f(m1 - mn1);
        float sum0 = 0.0f, sum1 = 0.0f;
        #pragma unroll
        for (int j = 0; j < 8; j++) {
            s[j][0] = ex2f(s[j][0] - mn0); s[j][1] = ex2f(s[j][1] - mn0);
            s[j][2] = ex2f(s[j][2] - mn1); s[j][3] = ex2f(s[j][3] - mn1);
            sum0 += s[j][0] + s[j][1];
            sum1 += s[j][2] + s[j][3];
        }
        sum0 += __shfl_xor_sync(0xffffffffu, sum0, 1);
        sum0 += __shfl_xor_sync(0xffffffffu, sum0, 2);
        sum1 += __shfl_xor_sync(0xffffffffu, sum1, 1);
        sum1 += __shfl_xor_sync(0xffffffffu, sum1, 2);
        l0 = l0 * al0 + sum0; m0 = mn0;
        l1 = l1 * al1 + sum1; m1 = mn1;

        // rescale O
        #pragma unroll
        for (int j = 0; j < 8; j++) {
            o[j][0] *= al0; o[j][1] *= al0;
            o[j][2] *= al1; o[j][3] *= al1;
        }

        // store P (tf32) to smem — warp-private rows
        #pragma unroll
        for (int j = 0; j < 8; j++) {
            int c = j * 8 + 2 * tg;
            *(float2*)&Ps[rw + g][c]     = make_float2(f2tf(s[j][0]), f2tf(s[j][1]));
            *(float2*)&Ps[rw + g + 8][c] = make_float2(f2tf(s[j][2]), f2tf(s[j][3]));
        }
        __syncwarp();   // P visible within warp (only this warp reads its rows)

        // ---- O += P * V ----
        #pragma unroll
        for (int kbf = 0; kbf < 8; kbf++) {
            int c = kbf * 8 + tg;
            unsigned pa0 = __float_as_uint(Ps[rw + g][c]);
            unsigned pa1 = __float_as_uint(Ps[rw + g + 8][c]);
            unsigned pa2 = __float_as_uint(Ps[rw + g][c + 4]);
            unsigned pa3 = __float_as_uint(Ps[rw + g + 8][c + 4]);
            #pragma unroll
            for (int j = 0; j < 8; j++) {
                unsigned b0 = __float_as_uint(Vs[kbase + kbf * 8 + tg][j * 8 + g]);
                unsigned b1 = __float_as_uint(Vs[kbase + kbf * 8 + tg + 4][j * 8 + g]);
                mma8(o[j], pa0, pa1, pa2, pa3, b0, b1);
            }
        }
    }

    // ---- epilogue: normalize and write ----
    float il0 = 1.0f / l0, il1 = 1.0f / l1;
    int row0 = qb * 128 + rw + g;
    #pragma unroll
    for (int j = 0; j < 8; j++) {
        int col = colbase + j * 8 + 2 * tg;
        *(float2*)&Out[(long)row0 * DIM + col] =
            make_float2(o[j][0] * il0, o[j][1] * il0);
        *(float2*)&Out[(long)(row0 + 8) * DIM + col] =
            make_float2(o[j][2] * il1, o[j][3] * il1);
    }
}

// ---------------------------------------------------------------------------
// kernel_launch
// ---------------------------------------------------------------------------
extern "C" void kernel_launch(void* const* d_in, const int* in_sizes, int n_in,
                              void* d_out, int out_size)
{
    const float* q  = (const float*)d_in[0];
    const float* k  = (const float*)d_in[1];
    const float* v  = (const float*)d_in[2];
    const float* Wq = (const float*)d_in[3];
    const float* bq = (const float*)d_in[4];
    const float* Wk = (const float*)d_in[5];
    const float* bk = (const float*)d_in[6];
    const float* Wv = (const float*)d_in[7];
    const float* bv = (const float*)d_in[8];
    const float* Wo = (const float*)d_in[9];
    const float* bo = (const float*)d_in[10];
    float* out = (float*)d_out;

    float *Qp, *Kp, *Vp, *Cp;
    cudaGetSymbolAddress((void**)&Qp, g_Q);
    cudaGetSymbolAddress((void**)&Kp, g_K);
    cudaGetSymbolAddress((void**)&Vp, g_V);
    cudaGetSymbolAddress((void**)&Cp, g_C);

    cudaFuncSetAttribute(attn_tc,
                         cudaFuncAttributeMaxDynamicSharedMemorySize,
                         ATT_SMEM_BYTES);

    dim3 gg(SEQ / 256, 16);
    dim3 ag(SEQ / 128, NH);
    dim3 blk(256);

    // projections: outputs rounded to tf32 (consumed by attention)
    gemm_tc<<<gg, blk>>>(q, Wq, bq, Qp, (long)DIM * DH, DH, 1);
    gemm_tc<<<gg, blk>>>(k, Wk, bk, Kp, (long)DIM * DH, DH, 1);
    gemm_tc<<<gg, blk>>>(v, Wv, bv, Vp, (long)DIM * DH, DH, 1);

    attn_tc<<<ag, blk, ATT_SMEM_BYTES>>>(Qp, Kp, Vp, Cp);

    // output projection: full fp32 outputs
    gemm_tc<<<gg, blk>>>(Cp, Wo, bo, out, 64L, DIM, 0);
}

// round 13
// speedup vs baseline: 3.7065x; 1.0441x over previous
#include <cuda_runtime.h>

#define SEQ 4096
#define DIM 1024
#define NH  16
#define DH  64

// Scratch (device globals; no allocation allowed)
__device__ float g_Q[SEQ * DIM];
__device__ float g_K[SEQ * DIM];
__device__ float g_V[SEQ * DIM];
__device__ float g_C[SEQ * DIM];

// ---------------------------------------------------------------------------
// helpers
// ---------------------------------------------------------------------------
__device__ __forceinline__ unsigned f2t(float f) {
    unsigned u; asm("cvt.rna.tf32.f32 %0, %1;" : "=r"(u) : "f"(f)); return u;
}
__device__ __forceinline__ float f2tf(float f) { return __uint_as_float(f2t(f)); }
__device__ __forceinline__ float ex2f(float x) {
    float r; asm("ex2.approx.ftz.f32 %0, %1;" : "=f"(r) : "f"(x)); return r;
}
__device__ __forceinline__ void mma8(float* c,
                                     unsigned a0, unsigned a1, unsigned a2, unsigned a3,
                                     unsigned b0, unsigned b1) {
    asm volatile(
        "mma.sync.aligned.m16n8k8.row.col.f32.tf32.tf32.f32 "
        "{%0,%1,%2,%3},{%4,%5,%6,%7},{%8,%9},{%0,%1,%2,%3};"
        : "+f"(c[0]), "+f"(c[1]), "+f"(c[2]), "+f"(c[3])
        : "r"(a0), "r"(a1), "r"(a2), "r"(a3), "r"(b0), "r"(b1));
}
__device__ __forceinline__ void cpa16(void* dst, const void* src) {
    unsigned d = (unsigned)__cvta_generic_to_shared(dst);
    asm volatile("cp.async.cg.shared.global [%0], [%1], 16;\n"
                 :: "r"(d), "l"(src) : "memory");
}
__device__ __forceinline__ void cp_commit() {
    asm volatile("cp.async.commit_group;\n" ::: "memory");
}
template <int N> __device__ __forceinline__ void cp_wait() {
    asm volatile("cp.async.wait_group %0;\n" :: "n"(N) : "memory");
}

struct GemmJob {
    const float* A;
    const float* B;
    const float* bias;
    float* C;
};

// ---------------------------------------------------------------------------
// tf32 tensor-core GEMM, cp.async double-buffered.
// CTA tile 256(M) x 64(N), K-step 32. 8 warps: warp tile 64(M) x 32(N).
// blockIdx.z selects one of up to 3 jobs (fused QKV projections).
// Raw fp32 staged via cp.async; RNA tf32 conversion at fragment load
// (numerically identical to converting at store).
//   per-head projections: W[H,D,DH] -> bTileStride = D*DH, bRowStride = DH
//   output projection:    Wo[D,D]   -> bTileStride = 64,   bRowStride = D
// ---------------------------------------------------------------------------
#define GAS 36   // As stride
#define GBS 72   // Bs stride
#define GEMM_SMEM_BYTES ((2 * 256 * GAS + 2 * 32 * GBS) * 4)

__global__ __launch_bounds__(256) void gemm_tc(GemmJob j0, GemmJob j1, GemmJob j2,
                                               long bTileStride, int bRowStride,
                                               int roundOut)
{
    extern __shared__ float gsm[];
    float (*As)[GAS] = (float(*)[GAS])gsm;                  // 2 x 256 x 36
    float (*Bs)[GBS] = (float(*)[GBS])(gsm + 2 * 256 * GAS); // 2 x 32 x 72

    const GemmJob job = (blockIdx.z == 0) ? j0 : ((blockIdx.z == 1) ? j1 : j2);

    const int tid  = threadIdx.x;
    const int lane = tid & 31;
    const int warp = tid >> 5;
    const int g    = lane >> 2;
    const int tg   = lane & 3;
    const int mw   = (warp >> 1) * 64;   // warp row base (0,64,128,192)
    const int nw   = (warp & 1) * 32;    // warp col base (0,32)
    const int m0   = blockIdx.x * 256;
    const int n0   = blockIdx.y * 64;
    const float* Bb = job.B + (long)blockIdx.y * bTileStride;

    const int brow = tid >> 3;           // 0..31
    const int bcol = (tid & 7) * 8;      // 0..56

    const float* Arow = job.A + (long)(m0 + tid) * DIM;

    // issue cp.async for K-step ks into buffer ks&1
    auto issue = [&](int ks) {
        int buf = (ks & 1) * 256;
        int bbuf = (ks & 1) * 32;
        const float* Ar = Arow + ks * 32;
        #pragma unroll
        for (int c = 0; c < 32; c += 4)
            cpa16(&As[buf + tid][c], Ar + c);
        const float* Br = Bb + (long)(ks * 32 + brow) * bRowStride + bcol;
        cpa16(&Bs[bbuf + brow][bcol], Br);
        cpa16(&Bs[bbuf + brow][bcol + 4], Br + 4);
    };

    issue(0); cp_commit();

    float acc[4][4][4] = {};

    for (int ks = 0; ks < DIM / 32; ks++) {
        cp_wait<0>();
        __syncthreads();   // tile ks visible; compute of ks-1 done (buffer reuse safe)

        if (ks + 1 < DIM / 32) issue(ks + 1);
        cp_commit();

        const int buf = (ks & 1) * 256;
        const int bbuf = (ks & 1) * 32;

        #pragma unroll
        for (int kb = 0; kb < 4; kb++) {
            unsigned a[4][4], b[4][2];
            #pragma unroll
            for (int i = 0; i < 4; i++) {
                int r = buf + mw + 16 * i + g;
                int c = kb * 8 + tg;
                a[i][0] = f2t(As[r][c]);
                a[i][1] = f2t(As[r + 8][c]);
                a[i][2] = f2t(As[r][c + 4]);
                a[i][3] = f2t(As[r + 8][c + 4]);
            }
            #pragma unroll
            for (int j = 0; j < 4; j++) {
                b[j][0] = f2t(Bs[bbuf + kb * 8 + tg][nw + 8 * j + g]);
                b[j][1] = f2t(Bs[bbuf + kb * 8 + tg + 4][nw + 8 * j + g]);
            }
            #pragma unroll
            for (int i = 0; i < 4; i++)
                #pragma unroll
                for (int j = 0; j < 4; j++)
                    mma8(acc[i][j], a[i][0], a[i][1], a[i][2], a[i][3],
                         b[j][0], b[j][1]);
        }
    }

    // epilogue + bias (+ optional tf32 rounding of outputs)
    #pragma unroll
    for (int i = 0; i < 4; i++) {
        int row = m0 + mw + 16 * i + g;
        #pragma unroll
        for (int j = 0; j < 4; j++) {
            int col = n0 + nw + 8 * j + 2 * tg;
            float b0v = job.bias[col], b1v = job.bias[col + 1];
            float v0 = acc[i][j][0] + b0v, v1 = acc[i][j][1] + b1v;
            float v2 = acc[i][j][2] + b0v, v3 = acc[i][j][3] + b1v;
            if (roundOut) {
                v0 = f2tf(v0); v1 = f2tf(v1); v2 = f2tf(v2); v3 = f2tf(v3);
            }
            *(float2*)&job.C[(long)row * DIM + col]       = make_float2(v0, v1);
            *(float2*)&job.C[(long)(row + 8) * DIM + col] = make_float2(v2, v3);
        }
    }
}

// ---------------------------------------------------------------------------
// Flash attention, tf32 tensor cores. CTA: 128 Q-rows x 1 head, 8 warps
// (warp = 16 Q-rows). KV block = 64 rows, cp.async double-buffered.
// Q/K/V arrive already tf32-rounded (projection GEMM epilogue).
// Softmax fully in registers (quad shuffles + ex2.approx).
// P routed via smem (warp-private rows -> __syncwarp only).
// ---------------------------------------------------------------------------
#define APS 68   // Ps stride (4g+tg pattern for A-frags)
#define AKS 68   // Ks stride (B-frag 4g+tg pattern)
#define AVS 72   // Vs stride (B-frag 8tg+g pattern)
#define ATT_SMEM_BYTES ((128 * APS + 2 * 64 * AKS + 2 * 64 * AVS) * 4)

__global__ __launch_bounds__(256) void attn_tc(const float* __restrict__ Q,
                                               const float* __restrict__ K,
                                               const float* __restrict__ V,
                                               float* __restrict__ Out)
{
    extern __shared__ float sm[];
    float (*Ps)[APS] = (float(*)[APS])sm;                         // 128 x 68
    float (*Ks)[AKS] = (float(*)[AKS])(sm + 128 * APS);           // 2 x 64 x 68
    float (*Vs)[AVS] = (float(*)[AVS])(sm + 128 * APS + 2 * 64 * AKS); // 2 x 64 x 72

    const int tid  = threadIdx.x;
    const int lane = tid & 31;
    const int warp = tid >> 5;
    const int g    = lane >> 2;
    const int tg   = lane & 3;
    const int qb   = blockIdx.x;
    const int h    = blockIdx.y;
    const int colbase = h * 64;
    const int rw   = warp * 16;          // warp's q-row base in tile

    const float L2E = 1.44269504f;

    const int krow = tid >> 2;           // 0..63
    const int kcol = (tid & 3) * 16;     // 0,16,32,48
    const float* Kbase = K + (long)krow * DIM + colbase + kcol;
    const float* Vbase = V + (long)krow * DIM + colbase + kcol;

    // ---- issue cp.async for KV block kb into buffer kb&1 ----
    auto issue = [&](int kb) {
        int kbase = (kb & 1) * 64;
        const float* Kr = Kbase + (long)kb * 64 * DIM;
        const float* Vr = Vbase + (long)kb * 64 * DIM;
        #pragma unroll
        for (int i = 0; i < 4; i++) {
            cpa16(&Ks[kbase + krow][kcol + 4 * i], Kr + 4 * i);
            cpa16(&Vs[kbase + krow][kcol + 4 * i], Vr + 4 * i);
        }
    };

    issue(0); cp_commit();

    // ---- stage Q tile (already tf32; scale by 1/32 — exact) ----
    {
        int row = tid >> 1;
        int cb  = (tid & 1) * 32;
        const float* Qr = Q + (long)(qb * 128 + row) * DIM + colbase + cb;
        #pragma unroll
        for (int c = 0; c < 32; c += 4) {
            float4 v = *(const float4*)(Qr + c);
            v.x *= 0.03125f; v.y *= 0.03125f; v.z *= 0.03125f; v.w *= 0.03125f;
            *(float4*)&Ps[row][cb + c] = v;
        }
    }
    __syncthreads();

    // ---- Q fragments in registers: q[kfrag e][4] ----
    unsigned q[8][4];
    #pragma unroll
    for (int e = 0; e < 8; e++) {
        int c = e * 8 + tg;
        q[e][0] = __float_as_uint(Ps[rw + g][c]);
        q[e][1] = __float_as_uint(Ps[rw + g + 8][c]);
        q[e][2] = __float_as_uint(Ps[rw + g][c + 4]);
        q[e][3] = __float_as_uint(Ps[rw + g + 8][c + 4]);
    }

    // online-softmax state (base-2 domain), rows g and g+8 of warp tile
    float m0 = -1e30f, m1 = -1e30f, l0 = 0.0f, l1 = 0.0f;
    float o[8][4] = {};

    for (int kb = 0; kb < SEQ / 64; kb++) {
        cp_wait<0>();      // KV block kb resident (this thread's groups)
        __syncthreads();   // CTA-wide: data visible; prev compute done

        if (kb + 1 < SEQ / 64) issue(kb + 1);   // overlaps compute below
        cp_commit();

        const int kbase = (kb & 1) * 64;

        // ---- S = Q * K^T : s[nfrag j][4] ----
        float s[8][4] = {};
        #pragma unroll
        for (int e = 0; e < 8; e++) {
            #pragma unroll
            for (int j = 0; j < 8; j++) {
                unsigned b0 = __float_as_uint(Ks[kbase + j * 8 + g][e * 8 + tg]);
                unsigned b1 = __float_as_uint(Ks[kbase + j * 8 + g][e * 8 + tg + 4]);
                mma8(s[j], q[e][0], q[e][1], q[e][2], q[e][3], b0, b1);
            }
        }

        // ---- softmax (registers, base-2) ----
        float mx0 = -1e30f, mx1 = -1e30f;
        #pragma unroll
        for (int j = 0; j < 8; j++) {
            s[j][0] *= L2E; s[j][1] *= L2E; s[j][2] *= L2E; s[j][3] *= L2E;
            mx0 = fmaxf(mx0, fmaxf(s[j][0], s[j][1]));
            mx1 = fmaxf(mx1, fmaxf(s[j][2], s[j][3]));
        }
        mx0 = fmaxf(mx0, __shfl_xor_sync(0xffffffffu, mx0, 1));
        mx0 = fmaxf(mx0, __shfl_xor_sync(0xffffffffu, mx0, 2));
        mx1 = fmaxf(mx1, __shfl_xor_sync(0xffffffffu, mx1, 1));
        mx1 = fmaxf(mx1, __shfl_xor_sync(0xffffffffu, mx1, 2));

        float mn0 = fmaxf(m0, mx0), mn1 = fmaxf(m1, mx1);
        float al0 = ex2f(m0 - mn0), al1 = ex2f(m1 - mn1);
        float sum0 = 0.0f, sum1 = 0.0f;
        #pragma unroll
        for (int j = 0; j < 8; j++) {
            s[j][0] = ex2f(s[j][0] - mn0); s[j][1] = ex2f(s[j][1] - mn0);
            s[j][2] = ex2f(s[j][2] - mn1); s[j][3] = ex2f(s[j][3] - mn1);
            sum0 += s[j][0] + s[j][1];
            sum1 += s[j][2] + s[j][3];
        }
        sum0 += __shfl_xor_sync(0xffffffffu, sum0, 1);
        sum0 += __shfl_xor_sync(0xffffffffu, sum0, 2);
        sum1 += __shfl_xor_sync(0xffffffffu, sum1, 1);
        sum1 += __shfl_xor_sync(0xffffffffu, sum1, 2);
        l0 = l0 * al0 + sum0; m0 = mn0;
        l1 = l1 * al1 + sum1; m1 = mn1;

        // rescale O
        #pragma unroll
        for (int j = 0; j < 8; j++) {
            o[j][0] *= al0; o[j][1] *= al0;
            o[j][2] *= al1; o[j][3] *= al1;
        }

        // store P (tf32) to smem — warp-private rows
        #pragma unroll
        for (int j = 0; j < 8; j++) {
            int c = j * 8 + 2 * tg;
            *(float2*)&Ps[rw + g][c]     = make_float2(f2tf(s[j][0]), f2tf(s[j][1]));
            *(float2*)&Ps[rw + g + 8][c] = make_float2(f2tf(s[j][2]), f2tf(s[j][3]));
        }
        __syncwarp();   // P visible within warp (only this warp reads its rows)

        // ---- O += P * V ----
        #pragma unroll
        for (int kbf = 0; kbf < 8; kbf++) {
            int c = kbf * 8 + tg;
            unsigned pa0 = __float_as_uint(Ps[rw + g][c]);
            unsigned pa1 = __float_as_uint(Ps[rw + g + 8][c]);
            unsigned pa2 = __float_as_uint(Ps[rw + g][c + 4]);
            unsigned pa3 = __float_as_uint(Ps[rw + g + 8][c + 4]);
            #pragma unroll
            for (int j = 0; j < 8; j++) {
                unsigned b0 = __float_as_uint(Vs[kbase + kbf * 8 + tg][j * 8 + g]);
                unsigned b1 = __float_as_uint(Vs[kbase + kbf * 8 + tg + 4][j * 8 + g]);
                mma8(o[j], pa0, pa1, pa2, pa3, b0, b1);
            }
        }
    }

    // ---- epilogue: normalize and write ----
    float il0 = 1.0f / l0, il1 = 1.0f / l1;
    int row0 = qb * 128 + rw + g;
    #pragma unroll
    for (int j = 0; j < 8; j++) {
        int col = colbase + j * 8 + 2 * tg;
        *(float2*)&Out[(long)row0 * DIM + col] =
            make_float2(o[j][0] * il0, o[j][1] * il0);
        *(float2*)&Out[(long)(row0 + 8) * DIM + col] =
            make_float2(o[j][2] * il1, o[j][3] * il1);
    }
}

// ---------------------------------------------------------------------------
// kernel_launch
// ---------------------------------------------------------------------------
extern "C" void kernel_launch(void* const* d_in, const int* in_sizes, int n_in,
                              void* d_out, int out_size)
{
    const float* q  = (const float*)d_in[0];
    const float* k  = (const float*)d_in[1];
    const float* v  = (const float*)d_in[2];
    const float* Wq = (const float*)d_in[3];
    const float* bq = (const float*)d_in[4];
    const float* Wk = (const float*)d_in[5];
    const float* bk = (const float*)d_in[6];
    const float* Wv = (const float*)d_in[7];
    const float* bv = (const float*)d_in[8];
    const float* Wo = (const float*)d_in[9];
    const float* bo = (const float*)d_in[10];
    float* out = (float*)d_out;

    float *Qp, *Kp, *Vp, *Cp;
    cudaGetSymbolAddress((void**)&Qp, g_Q);
    cudaGetSymbolAddress((void**)&Kp, g_K);
    cudaGetSymbolAddress((void**)&Vp, g_V);
    cudaGetSymbolAddress((void**)&Cp, g_C);

    cudaFuncSetAttribute(gemm_tc,
                         cudaFuncAttributeMaxDynamicSharedMemorySize,
                         GEMM_SMEM_BYTES);
    cudaFuncSetAttribute(attn_tc,
                         cudaFuncAttributeMaxDynamicSharedMemorySize,
                         ATT_SMEM_BYTES);

    dim3 blk(256);

    // Fused Q/K/V projections (one launch, blockIdx.z selects job),
    // outputs rounded to tf32 (consumed by attention).
    GemmJob jq = {q, Wq, bq, Qp};
    GemmJob jk = {k, Wk, bk, Kp};
    GemmJob jv = {v, Wv, bv, Vp};
    dim3 gqkv(SEQ / 256, 16, 3);
    gemm_tc<<<gqkv, blk, GEMM_SMEM_BYTES>>>(jq, jk, jv, (long)DIM * DH, DH, 1);

    // Attention
    dim3 ag(SEQ / 128, NH);
    attn_tc<<<ag, blk, ATT_SMEM_BYTES>>>(Qp, Kp, Vp, Cp);

    // Output projection: full fp32 outputs
    GemmJob jo = {Cp, Wo, bo, out};
    dim3 go(SEQ / 256, 16, 1);
    gemm_tc<<<go, blk, GEMM_SMEM_BYTES>>>(jo, jo, jo, 64L, DIM, 0);
}